// round 16
// baseline (speedup 1.0000x reference)
#include <cuda_runtime.h>
#include <cuda_bf16.h>
#include <math.h>

#define HIDDEN 256
#define HS     512
#define NHEADS 8
#define HDIM   64
#define NTOK   8
#define BATCH  8
#define HH     32
#define WW     32
#define PIXB   (HH*WW)        // 1024 pixels per batch
#define NPIX   (BATCH*PIXB)   // 8192
#define EPSV   1e-6f
#define ATTN_SCALE 0.125f     // 64^-0.5

typedef unsigned long long ull;
typedef unsigned int uint32;

// ---- packed f32x2 helpers (FFMA2) ----
__device__ __forceinline__ ull pack2(float lo, float hi) {
    ull r; asm("mov.b64 %0, {%1, %2};" : "=l"(r) : "f"(lo), "f"(hi)); return r;
}
__device__ __forceinline__ ull splat2(float x) {
    ull r; asm("mov.b64 %0, {%1, %1};" : "=l"(r) : "f"(x)); return r;
}
__device__ __forceinline__ void unpack2(ull p, float& lo, float& hi) {
    asm("mov.b64 {%0, %1}, %2;" : "=f"(lo), "=f"(hi) : "l"(p));
}
__device__ __forceinline__ void ffma2(ull& d, ull a, ull b) {
    asm("fma.rn.f32x2 %0, %1, %2, %0;" : "+l"(d) : "l"(a), "l"(b));
}

// ---- tf32 mma helpers ----
__device__ __forceinline__ uint32 cvt_tf32(float x) {
    uint32 r; asm("cvt.rna.tf32.f32 %0, %1;" : "=r"(r) : "f"(x)); return r;
}
__device__ __forceinline__ void mma_tf32(float* d, const uint32* a, const uint32* b) {
    asm volatile("mma.sync.aligned.m16n8k8.row.col.f32.tf32.tf32.f32 "
        "{%0,%1,%2,%3}, {%4,%5,%6,%7}, {%8,%9}, {%0,%1,%2,%3};"
        : "+f"(d[0]), "+f"(d[1]), "+f"(d[2]), "+f"(d[3])
        : "r"(a[0]), "r"(a[1]), "r"(a[2]), "r"(a[3]), "r"(b[0]), "r"(b[1]));
}

// ---------------- device scratch ----------------
__device__ float g_t[BATCH*HS];                  // silu(qe@w1+b1)
__device__ float g_wqc[BATCH*NHEADS*HIDDEN];     // [b][e][256]  (scale & rms_w folded)
// V weights as tf32 MMA A-fragments: [e][kk(32)][m(4)][lane(32)] uint4
__device__ uint4 g_wvt[NHEADS*32*4*32];
// w_out as tf32 MMA A-fragments: [kk(64)][mt(16 co-tiles)][lane(32)] uint4
__device__ uint4 g_wot[64*16*32];

// ---------------- K0: wide-parallel coalesced repacks + MLP layer 1 ----------------
__global__ __launch_bounds__(256) void k_front(
    const float* __restrict__ w_kv, const float* __restrict__ rms_w,
    const int* __restrict__ q, const float* __restrict__ emb,
    const float* __restrict__ w1, const float* __restrict__ b1,
    const float* __restrict__ w_out)
{
    extern __shared__ float sdyn[];
    __shared__ float qe[HIDDEN];
    __shared__ float part[4][64];
    int tid = threadIdx.x;
    int lane = tid & 31, warp = tid >> 5;
    int r4 = lane >> 2, c4 = lane & 3;

    if (blockIdx.x < 32) {
        // ---- wv repack: e = blk>>2, ch-quarter qd = blk&3 (64 rows) ----
        int e  = blockIdx.x >> 2;
        int qd = blockIdx.x & 3;
        const float4* wkv4 = (const float4*)w_kv;
        #pragma unroll
        for (int i = 0; i < 4; i++) {
            int idx = tid + i*256;             // 0..1023
            int row = idx >> 4, d4 = idx & 15; // row 0..63 local
            float4 v = wkv4[(size_t)(qd*64 + row)*256 + e*32 + 16 + d4];
            float rw = rms_w[qd*64 + row];
            float* dst = sdyn + row*65 + d4*4;
            dst[0] = rw*v.x; dst[1] = rw*v.y; dst[2] = rw*v.z; dst[3] = rw*v.w;
        }
        __syncthreads();
        #pragma unroll
        for (int u = 0; u < 4; u++) {
            int unit = warp*4 + u;             // 0..31
            int kkl = unit >> 2, m = unit & 3; // kkl 0..7 local
            int ch0 = kkl*8 + c4, d0 = m*16 + r4;
            uint4 o;
            o.x = cvt_tf32(sdyn[ch0*65 + d0]);
            o.y = cvt_tf32(sdyn[ch0*65 + d0 + 8]);
            o.z = cvt_tf32(sdyn[(ch0+4)*65 + d0]);
            o.w = cvt_tf32(sdyn[(ch0+4)*65 + d0 + 8]);
            g_wvt[((e*32 + qd*8 + kkl)*4 + m)*32 + lane] = o;
        }
        return;
    }
    if (blockIdx.x < 64) {
        // ---- wot repack: kb = blk-32 ----
        int kb = blockIdx.x - 32;
        const float4* wo4 = (const float4*)w_out;
        float4* s4 = (float4*)sdyn;            // stride 264 words = 66 float4
        #pragma unroll
        for (int i = 0; i < 4; i++) {
            int idx = tid + i*256;             // 0..1023
            int row = idx >> 6, c4i = idx & 63; // row 0..15 local
            s4[row*66 + c4i] = wo4[(size_t)(kb*16 + row)*64 + c4i];
        }
        __syncthreads();
        #pragma unroll
        for (int u = 0; u < 4; u++) {
            int unit = warp*4 + u;             // 0..31
            int kkl = unit >> 4, mt = unit & 15;  // kkl 0..1 local
            int k0 = kkl*8 + c4, co0 = mt*16 + r4;
            uint4 o;
            o.x = cvt_tf32(sdyn[k0*264 + co0]);
            o.y = cvt_tf32(sdyn[k0*264 + co0 + 8]);
            o.z = cvt_tf32(sdyn[(k0+4)*264 + co0]);
            o.w = cvt_tf32(sdyn[(k0+4)*264 + co0 + 8]);
            g_wot[((kb*2 + kkl)*16 + mt)*32 + lane] = o;
        }
        return;
    }

    // ---- MLP layer 1 ----
    int idx = blockIdx.x - 64;           // 0..63
    int b  = idx >> 3;
    int c0 = (idx & 7) * 64;
    qe[tid] = emb[q[b]*HIDDEN + tid];
    __syncthreads();

    int col = tid & 63, ks = tid >> 6;
    float acc = 0.f;
    #pragma unroll 1
    for (int u0 = 0; u0 < 64; u0 += 16) {
        float v[16];
        #pragma unroll
        for (int u = 0; u < 16; u++)
            v[u] = w1[(size_t)(ks*64 + u0 + u)*HS + c0 + col];
        #pragma unroll
        for (int u = 0; u < 16; u++)
            acc = fmaf(qe[ks*64 + u0 + u], v[u], acc);
    }
    part[ks][col] = acc;
    __syncthreads();
    if (tid < 64) {
        float s = part[0][tid] + part[1][tid] + part[2][tid] + part[3][tid] + b1[c0 + tid];
        g_t[b*HS + c0 + tid] = s / (1.f + expf(-s));
    }
}

// ---------------- K1: fused MLP layer 2 + wqc (coalesced K-weight staging) ----------------
__global__ __launch_bounds__(256) void k_mid(
    const float* __restrict__ w2, const float* __restrict__ b2,
    const float* __restrict__ w_kv, const float* __restrict__ rms_w)
{
    extern __shared__ float sKv[];       // [256ch][64d] stride 65 = 66560 B
    __shared__ float t_s[HS];
    __shared__ float part[4][64];
    __shared__ float qh_s[HDIM];
    int tid = threadIdx.x;
    int b = blockIdx.x >> 3, e = blockIdx.x & 7;

    t_s[tid]       = g_t[b*HS + tid];
    t_s[tid + 256] = g_t[b*HS + tid + 256];

    {
        const float4* wkv4 = (const float4*)w_kv;
        #pragma unroll 4
        for (int i = 0; i < 16; i++) {
            int idx = tid + i*256;           // 0..4095
            int row = idx >> 4, d4 = idx & 15;
            float4 v = wkv4[(size_t)row*256 + e*32 + d4];
            float* dst = sKv + row*65 + d4*4;
            dst[0] = v.x; dst[1] = v.y; dst[2] = v.z; dst[3] = v.w;
        }
    }
    __syncthreads();

    int d = tid & 63, ks = tid >> 6;
    float acc = 0.f;
    #pragma unroll 1
    for (int u0 = 0; u0 < 128; u0 += 16) {
        float v[16];
        #pragma unroll
        for (int u = 0; u < 16; u++)
            v[u] = w2[(size_t)(ks*128 + u0 + u)*HS + e*HDIM + d];
        #pragma unroll
        for (int u = 0; u < 16; u++)
            acc = fmaf(t_s[ks*128 + u0 + u], v[u], acc);
    }
    part[ks][d] = acc;
    __syncthreads();
    if (tid < 64)
        qh_s[tid] = part[0][tid] + part[1][tid] + part[2][tid] + part[3][tid] + b2[e*HDIM + tid];
    __syncthreads();

    {
        int ch = tid;
        float s = 0.f;
        const float* row = sKv + ch*65;
        #pragma unroll 16
        for (int dd = 0; dd < HDIM; dd++)
            s = fmaf(qh_s[dd], row[dd], s);
        g_wqc[(b*NHEADS + e)*HIDDEN + ch] = s * rms_w[ch] * ATTN_SCALE;
    }
}

// ---------------- K2: FULLY FUSED kernel — smem diet for 3 blocks/SM ----------------
// Block = one (b,h) row of 32 pixels, 256 threads (8 warps).
// smem 66560 B -> 3 blocks/SM (24 warps):
//   swq2 ull[1024]  @0       (8192)   dead after pass A
//   a2_s ull[1024]  @8192    (8192)   live through phase B
//   s_s  f[2048]    @16384   (8192)   dots -> softmax IN PLACE -> repacked -> dead
//   rms  f[256]     @24576   (1024)
//   cb_t uint32     @25600   (40960)  tf32 cbar chunk [8e*32ch][40]
//   hst  uint32     @0       OVERLAYS EVERYTHING after last phase-C barrier
//                            [32px][516] tf32 = 66048 <= 66560
__global__ __launch_bounds__(256, 3) void k_attn3(
    const float* __restrict__ c, const float* __restrict__ b_out,
    float* __restrict__ out)
{
    extern __shared__ ull smu[];
    ull*   swq2  = smu;                               // [ch][4 head-pairs]
    ull*   a2_s  = smu + 1024;                        // [n][4 head-pairs][lane]
    float* s_s   = (float*)(smu + 2048);              // dots / attn in place
    float* rms_s = s_s + 2048;                        // [n][p]
    uint32* cb_t = (uint32*)((char*)smu + 25600);     // tf32 cbar chunk [e*32+ch][40]
    uint32* hst  = (uint32*)smu;                      // overlay: tf32 H [32px][516]

    int b = blockIdx.x >> 5;
    int h = blockIdx.x & 31;
    int tid = threadIdx.x;
    int warp = tid >> 5, lane = tid & 31;
    int r4 = lane >> 2, c4 = lane & 3;

    for (int i = tid; i < HIDDEN*4; i += 256) {
        int ch = i >> 2, p = i & 3;
        float lo = g_wqc[b*NHEADS*HIDDEN + (2*p)*HIDDEN + ch];
        float hi = g_wqc[b*NHEADS*HIDDEN + (2*p+1)*HIDDEN + ch];
        swq2[i] = pack2(lo, hi);
    }
    __syncthreads();

    // ---- pass A: sumsq + dots (warp = token n, lane = pixel p), MLP=32 ----
    {
        const float* cp = c + ((size_t)(b*NTOK + warp)*HIDDEN)*PIXB + h*WW + lane;
        float ss = 0.f;
        ull sd2[4] = {0ull, 0ull, 0ull, 0ull};
        #pragma unroll 1
        for (int ch0 = 0; ch0 < HIDDEN; ch0 += 32) {
            float v[32];
            #pragma unroll
            for (int u = 0; u < 32; u++) v[u] = cp[(size_t)(ch0+u)*PIXB];
            #pragma unroll
            for (int u = 0; u < 32; u++) {
                int ch = ch0 + u;
                ss = fmaf(v[u], v[u], ss);
                ull v2 = splat2(v[u]);
                ulonglong2 s01 = *(const ulonglong2*)(swq2 + ch*4);
                ulonglong2 s23 = *(const ulonglong2*)(swq2 + ch*4 + 2);
                ffma2(sd2[0], v2, s01.x);
                ffma2(sd2[1], v2, s01.y);
                ffma2(sd2[2], v2, s23.x);
                ffma2(sd2[3], v2, s23.y);
            }
        }
        rms_s[warp*32 + lane] = rsqrtf(ss*(1.0f/HIDDEN) + EPSV);
        #pragma unroll
        for (int p = 0; p < 4; p++) {
            float lo, hi; unpack2(sd2[p], lo, hi);
            s_s[((2*p)*NTOK + warp)*32 + lane]   = lo;
            s_s[((2*p+1)*NTOK + warp)*32 + lane] = hi;
        }
    }
    __syncthreads();

    // ---- softmax (in place: each thread owns its 8 slots) ----
    {
        int e = tid >> 5, p = tid & 31;
        float d[NTOK], m = -1e30f;
        #pragma unroll
        for (int n = 0; n < NTOK; n++) {
            d[n] = s_s[(e*NTOK + n)*32 + p] * rms_s[n*32 + p];
            m = fmaxf(m, d[n]);
        }
        float sum = 0.f;
        #pragma unroll
        for (int n = 0; n < NTOK; n++) { d[n] = expf(d[n] - m); sum += d[n]; }
        float inv = 1.f / sum;
        #pragma unroll
        for (int n = 0; n < NTOK; n++)
            s_s[(e*NTOK + n)*32 + p] = d[n] * inv * rms_s[n*32 + p];
    }
    __syncthreads();

    // repack attn pair-major: a2_s[(n*4+p)*32+lane]
    for (int i = tid; i < 1024; i += 256) {
        int n = i >> 7, p = (i >> 5) & 3, l2 = i & 31;
        float lo = s_s[((2*p)*NTOK + n)*32 + l2];
        float hi = s_s[((2*p+1)*NTOK + n)*32 + l2];
        a2_s[i] = pack2(lo, hi);
    }
    __syncthreads();

    // ---- chunked (32-ch) cbar + per-head V-GEMM via tf32 MMA ----
    float D[4][4][4];
    #pragma unroll
    for (int m = 0; m < 4; m++)
        #pragma unroll
        for (int n = 0; n < 4; n++)
            #pragma unroll
            for (int t = 0; t < 4; t++) D[m][n][t] = 0.f;

    for (int cbk = 0; cbk < 8; cbk++) {
        // phase B: cbar chunk (32 ch), warp covers 4 channels; 2 channels batched
        #pragma unroll
        for (int cc = 0; cc < 2; cc++) {
            int chl = warp*4 + cc*2;
            int ch  = cbk*32 + chl;
            const float* cp = c + ((size_t)(b*NTOK)*HIDDEN + ch)*PIXB + h*WW + lane;
            float v[2][NTOK];
            #pragma unroll
            for (int n = 0; n < NTOK; n++) {
                v[0][n] = cp[(size_t)n*HIDDEN*PIXB];
                v[1][n] = cp[(size_t)n*HIDDEN*PIXB + PIXB];
            }
            #pragma unroll
            for (int s = 0; s < 2; s++) {
                ull cb2[4] = {0ull, 0ull, 0ull, 0ull};
                #pragma unroll
                for (int n = 0; n < NTOK; n++) {
                    ull v2 = splat2(v[s][n]);
                    ffma2(cb2[0], v2, a2_s[(n*4 + 0)*32 + lane]);
                    ffma2(cb2[1], v2, a2_s[(n*4 + 1)*32 + lane]);
                    ffma2(cb2[2], v2, a2_s[(n*4 + 2)*32 + lane]);
                    ffma2(cb2[3], v2, a2_s[(n*4 + 3)*32 + lane]);
                }
                #pragma unroll
                for (int p = 0; p < 4; p++) {
                    float lo, hi; unpack2(cb2[p], lo, hi);
                    cb_t[((2*p)*32 + chl + s)*40 + lane]   = cvt_tf32(lo);
                    cb_t[((2*p+1)*32 + chl + s)*40 + lane] = cvt_tf32(hi);
                }
            }
        }
        __syncthreads();

        // phase C: warp = head e; D += Wv_e^T @ cbar_e over this 32-ch chunk
        #pragma unroll
        for (int kt = 0; kt < 4; kt++) {
            uint32 bfr[4][2];
            #pragma unroll
            for (int n = 0; n < 4; n++) {
                bfr[n][0] = cb_t[(warp*32 + kt*8 + c4)*40 + n*8 + r4];
                bfr[n][1] = cb_t[(warp*32 + kt*8 + c4 + 4)*40 + n*8 + r4];
            }
            #pragma unroll
            for (int m = 0; m < 4; m++) {
                uint4 af = g_wvt[((warp*32 + cbk*4 + kt)*4 + m)*32 + lane];
                #pragma unroll
                for (int n = 0; n < 4; n++)
                    mma_tf32(D[m][n], (const uint32*)&af, bfr[n]);
            }
        }
        __syncthreads();
    }

    // ---- stage H as tf32 into hst[px][516 + d'] (overlays ALL dead smem) ----
    #pragma unroll
    for (int m = 0; m < 4; m++) {
        int d_lo = warp*HDIM + m*16 + r4;
        #pragma unroll
        for (int n = 0; n < 4; n++) {
            int pxa = n*8 + 2*c4;
            hst[pxa*516 + d_lo]           = cvt_tf32(D[m][n][0]);
            hst[(pxa+1)*516 + d_lo]       = cvt_tf32(D[m][n][1]);
            hst[pxa*516 + d_lo + 8]       = cvt_tf32(D[m][n][2]);
            hst[(pxa+1)*516 + d_lo + 8]   = cvt_tf32(D[m][n][3]);
        }
    }
    __syncthreads();

    // ---- out-GEMM via tf32 mma, af batched 4 kk deep ----
    float D2[2][4][4];
    #pragma unroll
    for (int m = 0; m < 2; m++)
        #pragma unroll
        for (int n = 0; n < 4; n++)
            #pragma unroll
            for (int t = 0; t < 4; t++) D2[m][n][t] = 0.f;

    #pragma unroll 1
    for (int g = 0; g < 16; g++) {
        uint4 af[8];
        #pragma unroll
        for (int j = 0; j < 4; j++) {
            int kk = g*4 + j;
            af[2*j]   = g_wot[(kk*16 + warp*2    )*32 + lane];
            af[2*j+1] = g_wot[(kk*16 + warp*2 + 1)*32 + lane];
        }
        #pragma unroll
        for (int j = 0; j < 4; j++) {
            int kk = g*4 + j;
            uint32 bfr[4][2];
            #pragma unroll
            for (int n = 0; n < 4; n++) {
                bfr[n][0] = hst[(n*8 + r4)*516 + kk*8 + c4];
                bfr[n][1] = hst[(n*8 + r4)*516 + kk*8 + c4 + 4];
            }
            #pragma unroll
            for (int n = 0; n < 4; n++) {
                mma_tf32(D2[0][n], (const uint32*)&af[2*j],   bfr[n]);
                mma_tf32(D2[1][n], (const uint32*)&af[2*j+1], bfr[n]);
            }
        }
    }

    // epilogue
    #pragma unroll
    for (int m = 0; m < 2; m++) {
        int co0 = warp*32 + m*16 + r4;
        float bl = b_out[co0], bh = b_out[co0 + 8];
        #pragma unroll
        for (int n = 0; n < 4; n++) {
            int px = n*8 + 2*c4;
            float* d0 = out + ((size_t)(b*HIDDEN + co0))*PIXB + h*WW + px;
            float* d1 = out + ((size_t)(b*HIDDEN + co0 + 8))*PIXB + h*WW + px;
            *(float2*)d0 = make_float2(D2[m][n][0] + bl, D2[m][n][1] + bl);
            *(float2*)d1 = make_float2(D2[m][n][2] + bh, D2[m][n][3] + bh);
        }
    }
}

// ---------------- launch ----------------
extern "C" void kernel_launch(void* const* d_in, const int* in_sizes, int n_in,
                              void* d_out, int out_size)
{
    const int*   q     = (const int*)  d_in[0];
    const float* c     = (const float*)d_in[1];
    const float* rms_w = (const float*)d_in[2];
    const float* emb   = (const float*)d_in[3];
    const float* w1    = (const float*)d_in[4];
    const float* b1    = (const float*)d_in[5];
    const float* w2    = (const float*)d_in[6];
    const float* b2    = (const float*)d_in[7];
    const float* w_kv  = (const float*)d_in[8];
    const float* w_out = (const float*)d_in[9];
    const float* b_out = (const float*)d_in[10];
    float* out = (float*)d_out;

    const int FRONT_SMEM = 16*264*4;        // 16896 B
    const int MID_SMEM   = 256*65*4;        // 66560 B
    const int ATTN_SMEM  = 66560;           // B — 3 blocks/SM
    cudaFuncSetAttribute(k_front, cudaFuncAttributeMaxDynamicSharedMemorySize, FRONT_SMEM);
    cudaFuncSetAttribute(k_mid,   cudaFuncAttributeMaxDynamicSharedMemorySize, MID_SMEM);
    cudaFuncSetAttribute(k_attn3, cudaFuncAttributeMaxDynamicSharedMemorySize, ATTN_SMEM);

    k_front<<<64 + 64, 256, FRONT_SMEM>>>(w_kv, rms_w, q, emb, w1, b1, w_out);
    k_mid  <<<BATCH*NHEADS, 256, MID_SMEM>>>(w2, b2, w_kv, rms_w);
    k_attn3<<<BATCH*HH, 256, ATTN_SMEM>>>(c, b_out, out);
}

// round 17
// speedup vs baseline: 3.5104x; 3.5104x over previous
#include <cuda_runtime.h>
#include <cuda_bf16.h>
#include <math.h>

#define HIDDEN 256
#define HS     512
#define NHEADS 8
#define HDIM   64
#define NTOK   8
#define BATCH  8
#define HH     32
#define WW     32
#define PIXB   (HH*WW)        // 1024 pixels per batch
#define NPIX   (BATCH*PIXB)   // 8192
#define EPSV   1e-6f
#define ATTN_SCALE 0.125f     // 64^-0.5

typedef unsigned long long ull;
typedef unsigned int uint32;

// ---- packed f32x2 helpers (FFMA2) ----
__device__ __forceinline__ ull pack2(float lo, float hi) {
    ull r; asm("mov.b64 %0, {%1, %2};" : "=l"(r) : "f"(lo), "f"(hi)); return r;
}
__device__ __forceinline__ ull splat2(float x) {
    ull r; asm("mov.b64 %0, {%1, %1};" : "=l"(r) : "f"(x)); return r;
}
__device__ __forceinline__ void unpack2(ull p, float& lo, float& hi) {
    asm("mov.b64 {%0, %1}, %2;" : "=f"(lo), "=f"(hi) : "l"(p));
}
__device__ __forceinline__ void ffma2(ull& d, ull a, ull b) {
    asm("fma.rn.f32x2 %0, %1, %2, %0;" : "+l"(d) : "l"(a), "l"(b));
}

// ---- tf32 mma helpers ----
__device__ __forceinline__ uint32 cvt_tf32(float x) {
    uint32 r; asm("cvt.rna.tf32.f32 %0, %1;" : "=r"(r) : "f"(x)); return r;
}
__device__ __forceinline__ void mma_tf32(float* d, const uint32* a, const uint32* b) {
    asm volatile("mma.sync.aligned.m16n8k8.row.col.f32.tf32.tf32.f32 "
        "{%0,%1,%2,%3}, {%4,%5,%6,%7}, {%8,%9}, {%0,%1,%2,%3};"
        : "+f"(d[0]), "+f"(d[1]), "+f"(d[2]), "+f"(d[3])
        : "r"(a[0]), "r"(a[1]), "r"(a[2]), "r"(a[3]), "r"(b[0]), "r"(b[1]));
}

// ---------------- device scratch ----------------
__device__ float g_t[BATCH*HS];                  // silu(qe@w1+b1)
__device__ float g_wqc[BATCH*NHEADS*HIDDEN];     // [b][e][256]  (scale & rms_w folded)
// V weights as tf32 MMA A-fragments: [e][kk(32)][m(4)][lane(32)] uint4
__device__ uint4 g_wvt[NHEADS*32*4*32];
// w_out as tf32 MMA A-fragments: [kk(64)][mt(16 co-tiles)][lane(32)] uint4
__device__ uint4 g_wot[64*16*32];

// ---------------- K0: wide-parallel coalesced repacks + MLP layer 1 ----------------
// blocks [0,32):   wv repack, block = (e, ch-quarter): stage [64ch][64d] stride 65
// blocks [32,64):  wot repack, block = kb (2 kk = 16 k-rows): stage [16k][256co] stride 264
// blocks [64,128): MLP layer 1 (b, 64-col chunk)
__global__ __launch_bounds__(256) void k_front(
    const float* __restrict__ w_kv, const float* __restrict__ rms_w,
    const int* __restrict__ q, const float* __restrict__ emb,
    const float* __restrict__ w1, const float* __restrict__ b1,
    const float* __restrict__ w_out)
{
    extern __shared__ float sdyn[];
    __shared__ float qe[HIDDEN];
    __shared__ float part[4][64];
    int tid = threadIdx.x;
    int lane = tid & 31, warp = tid >> 5;
    int r4 = lane >> 2, c4 = lane & 3;

    if (blockIdx.x < 32) {
        int e  = blockIdx.x >> 2;
        int qd = blockIdx.x & 3;
        const float4* wkv4 = (const float4*)w_kv;
        #pragma unroll
        for (int i = 0; i < 4; i++) {
            int idx = tid + i*256;             // 0..1023
            int row = idx >> 4, d4 = idx & 15; // row 0..63 local
            float4 v = wkv4[(size_t)(qd*64 + row)*256 + e*32 + 16 + d4];
            float rw = rms_w[qd*64 + row];
            float* dst = sdyn + row*65 + d4*4;
            dst[0] = rw*v.x; dst[1] = rw*v.y; dst[2] = rw*v.z; dst[3] = rw*v.w;
        }
        __syncthreads();
        #pragma unroll
        for (int u = 0; u < 4; u++) {
            int unit = warp*4 + u;             // 0..31
            int kkl = unit >> 2, m = unit & 3; // kkl 0..7 local
            int ch0 = kkl*8 + c4, d0 = m*16 + r4;
            uint4 o;
            o.x = cvt_tf32(sdyn[ch0*65 + d0]);
            o.y = cvt_tf32(sdyn[ch0*65 + d0 + 8]);
            o.z = cvt_tf32(sdyn[(ch0+4)*65 + d0]);
            o.w = cvt_tf32(sdyn[(ch0+4)*65 + d0 + 8]);
            g_wvt[((e*32 + qd*8 + kkl)*4 + m)*32 + lane] = o;
        }
        return;
    }
    if (blockIdx.x < 64) {
        int kb = blockIdx.x - 32;
        const float4* wo4 = (const float4*)w_out;
        float4* s4 = (float4*)sdyn;            // stride 264 words = 66 float4
        #pragma unroll
        for (int i = 0; i < 4; i++) {
            int idx = tid + i*256;             // 0..1023
            int row = idx >> 6, c4i = idx & 63; // row 0..15 local
            s4[row*66 + c4i] = wo4[(size_t)(kb*16 + row)*64 + c4i];
        }
        __syncthreads();
        #pragma unroll
        for (int u = 0; u < 4; u++) {
            int unit = warp*4 + u;             // 0..31
            int kkl = unit >> 4, mt = unit & 15;  // kkl 0..1 local
            int k0 = kkl*8 + c4, co0 = mt*16 + r4;
            uint4 o;
            o.x = cvt_tf32(sdyn[k0*264 + co0]);
            o.y = cvt_tf32(sdyn[k0*264 + co0 + 8]);
            o.z = cvt_tf32(sdyn[(k0+4)*264 + co0]);
            o.w = cvt_tf32(sdyn[(k0+4)*264 + co0 + 8]);
            g_wot[((kb*2 + kkl)*16 + mt)*32 + lane] = o;
        }
        return;
    }

    // ---- MLP layer 1 ----
    int idx = blockIdx.x - 64;           // 0..63
    int b  = idx >> 3;
    int c0 = (idx & 7) * 64;
    qe[tid] = emb[q[b]*HIDDEN + tid];
    __syncthreads();

    int col = tid & 63, ks = tid >> 6;
    float acc = 0.f;
    #pragma unroll 1
    for (int u0 = 0; u0 < 64; u0 += 16) {
        float v[16];
        #pragma unroll
        for (int u = 0; u < 16; u++)
            v[u] = w1[(size_t)(ks*64 + u0 + u)*HS + c0 + col];
        #pragma unroll
        for (int u = 0; u < 16; u++)
            acc = fmaf(qe[ks*64 + u0 + u], v[u], acc);
    }
    part[ks][col] = acc;
    __syncthreads();
    if (tid < 64) {
        float s = part[0][tid] + part[1][tid] + part[2][tid] + part[3][tid] + b1[c0 + tid];
        g_t[b*HS + c0 + tid] = s / (1.f + expf(-s));
    }
}

// ---------------- K1: fused MLP layer 2 + wqc (coalesced K-weight staging) ----------------
__global__ __launch_bounds__(256) void k_mid(
    const float* __restrict__ w2, const float* __restrict__ b2,
    const float* __restrict__ w_kv, const float* __restrict__ rms_w)
{
    extern __shared__ float sKv[];       // [256ch][64d] stride 65 = 66560 B
    __shared__ float t_s[HS];
    __shared__ float part[4][64];
    __shared__ float qh_s[HDIM];
    int tid = threadIdx.x;
    int b = blockIdx.x >> 3, e = blockIdx.x & 7;

    t_s[tid]       = g_t[b*HS + tid];
    t_s[tid + 256] = g_t[b*HS + tid + 256];

    {
        const float4* wkv4 = (const float4*)w_kv;
        #pragma unroll 4
        for (int i = 0; i < 16; i++) {
            int idx = tid + i*256;           // 0..4095
            int row = idx >> 4, d4 = idx & 15;
            float4 v = wkv4[(size_t)row*256 + e*32 + d4];
            float* dst = sKv + row*65 + d4*4;
            dst[0] = v.x; dst[1] = v.y; dst[2] = v.z; dst[3] = v.w;
        }
    }
    __syncthreads();

    int d = tid & 63, ks = tid >> 6;
    float acc = 0.f;
    #pragma unroll 1
    for (int u0 = 0; u0 < 128; u0 += 16) {
        float v[16];
        #pragma unroll
        for (int u = 0; u < 16; u++)
            v[u] = w2[(size_t)(ks*128 + u0 + u)*HS + e*HDIM + d];
        #pragma unroll
        for (int u = 0; u < 16; u++)
            acc = fmaf(t_s[ks*128 + u0 + u], v[u], acc);
    }
    part[ks][d] = acc;
    __syncthreads();
    if (tid < 64)
        qh_s[tid] = part[0][tid] + part[1][tid] + part[2][tid] + part[3][tid] + b2[e*HDIM + tid];
    __syncthreads();

    {
        int ch = tid;
        float s = 0.f;
        const float* row = sKv + ch*65;
        #pragma unroll 16
        for (int dd = 0; dd < HDIM; dd++)
            s = fmaf(qh_s[dd], row[dd], s);
        g_wqc[(b*NHEADS + e)*HIDDEN + ch] = s * rms_w[ch] * ATTN_SCALE;
    }
}

// ---------------- K2: FULLY FUSED kernel (round-14 champion + phase-B batch 32) ----------------
// Block = one (b,h) row of 32 pixels, 256 threads (8 warps). smem 100352 B, 2 blocks/SM.
__global__ __launch_bounds__(256, 2) void k_attn3(
    const float* __restrict__ c, const float* __restrict__ b_out,
    float* __restrict__ out)
{
    extern __shared__ ull smu[];
    ull*   swq2  = smu;              // [ch][4 head-pairs]
    ull*   a2_s  = smu + 1024;       // [n][4 head-pairs][lane]
    float* fb    = (float*)(smu + 2048);
    float* s_s   = fb;               // dots [e][n][p]
    float* rms_s = fb + 2048;        // [n][p]
    float* a_s   = fb + 2304;        // attn*inv_rms [e][n][p]
    uint32* cb_t = (uint32*)((char*)smu + 33792);     // tf32 cbar chunk [e*32+ch][40]
    uint32* hst  = (uint32*)((char*)smu + 33792);     // overlay: tf32 H [32px][516]

    int b = blockIdx.x >> 5;
    int h = blockIdx.x & 31;
    int tid = threadIdx.x;
    int warp = tid >> 5, lane = tid & 31;
    int r4 = lane >> 2, c4 = lane & 3;

    for (int i = tid; i < HIDDEN*4; i += 256) {
        int ch = i >> 2, p = i & 3;
        float lo = g_wqc[b*NHEADS*HIDDEN + (2*p)*HIDDEN + ch];
        float hi = g_wqc[b*NHEADS*HIDDEN + (2*p+1)*HIDDEN + ch];
        swq2[i] = pack2(lo, hi);
    }
    __syncthreads();

    // ---- pass A: sumsq + dots (warp = token n, lane = pixel p), MLP=32 ----
    {
        const float* cp = c + ((size_t)(b*NTOK + warp)*HIDDEN)*PIXB + h*WW + lane;
        float ss = 0.f;
        ull sd2[4] = {0ull, 0ull, 0ull, 0ull};
        #pragma unroll 1
        for (int ch0 = 0; ch0 < HIDDEN; ch0 += 32) {
            float v[32];
            #pragma unroll
            for (int u = 0; u < 32; u++) v[u] = cp[(size_t)(ch0+u)*PIXB];
            #pragma unroll
            for (int u = 0; u < 32; u++) {
                int ch = ch0 + u;
                ss = fmaf(v[u], v[u], ss);
                ull v2 = splat2(v[u]);
                ulonglong2 s01 = *(const ulonglong2*)(swq2 + ch*4);
                ulonglong2 s23 = *(const ulonglong2*)(swq2 + ch*4 + 2);
                ffma2(sd2[0], v2, s01.x);
                ffma2(sd2[1], v2, s01.y);
                ffma2(sd2[2], v2, s23.x);
                ffma2(sd2[3], v2, s23.y);
            }
        }
        rms_s[warp*32 + lane] = rsqrtf(ss*(1.0f/HIDDEN) + EPSV);
        #pragma unroll
        for (int p = 0; p < 4; p++) {
            float lo, hi; unpack2(sd2[p], lo, hi);
            s_s[((2*p)*NTOK + warp)*32 + lane]   = lo;
            s_s[((2*p+1)*NTOK + warp)*32 + lane] = hi;
        }
    }
    __syncthreads();

    // ---- softmax ----
    {
        int e = tid >> 5, p = tid & 31;
        float d[NTOK], m = -1e30f;
        #pragma unroll
        for (int n = 0; n < NTOK; n++) {
            d[n] = s_s[(e*NTOK + n)*32 + p] * rms_s[n*32 + p];
            m = fmaxf(m, d[n]);
        }
        float sum = 0.f;
        #pragma unroll
        for (int n = 0; n < NTOK; n++) { d[n] = expf(d[n] - m); sum += d[n]; }
        float inv = 1.f / sum;
        #pragma unroll
        for (int n = 0; n < NTOK; n++)
            a_s[(e*NTOK + n)*32 + p] = d[n] * inv * rms_s[n*32 + p];
    }
    __syncthreads();

    for (int i = tid; i < 1024; i += 256) {
        int n = i >> 7, p = (i >> 5) & 3, l2 = i & 31;
        float lo = a_s[((2*p)*NTOK + n)*32 + l2];
        float hi = a_s[((2*p+1)*NTOK + n)*32 + l2];
        a2_s[i] = pack2(lo, hi);
    }
    __syncthreads();

    // ---- chunked (32-ch) cbar + per-head V-GEMM via tf32 MMA ----
    float D[4][4][4];
    #pragma unroll
    for (int m = 0; m < 4; m++)
        #pragma unroll
        for (int n = 0; n < 4; n++)
            #pragma unroll
            for (int t = 0; t < 4; t++) D[m][n][t] = 0.f;

    for (int cbk = 0; cbk < 8; cbk++) {
        // phase B: cbar chunk (32 ch), warp covers 4 channels; ALL 4 channels batched (MLP=32)
        {
            int chl0 = warp*4;
            int ch   = cbk*32 + chl0;
            const float* cp = c + ((size_t)(b*NTOK)*HIDDEN + ch)*PIXB + h*WW + lane;
            float v[4][NTOK];
            #pragma unroll
            for (int n = 0; n < NTOK; n++) {
                v[0][n] = cp[(size_t)n*HIDDEN*PIXB];
                v[1][n] = cp[(size_t)n*HIDDEN*PIXB + PIXB];
                v[2][n] = cp[(size_t)n*HIDDEN*PIXB + 2*PIXB];
                v[3][n] = cp[(size_t)n*HIDDEN*PIXB + 3*PIXB];
            }
            #pragma unroll
            for (int s = 0; s < 4; s++) {
                ull cb2[4] = {0ull, 0ull, 0ull, 0ull};
                #pragma unroll
                for (int n = 0; n < NTOK; n++) {
                    ull v2 = splat2(v[s][n]);
                    ffma2(cb2[0], v2, a2_s[(n*4 + 0)*32 + lane]);
                    ffma2(cb2[1], v2, a2_s[(n*4 + 1)*32 + lane]);
                    ffma2(cb2[2], v2, a2_s[(n*4 + 2)*32 + lane]);
                    ffma2(cb2[3], v2, a2_s[(n*4 + 3)*32 + lane]);
                }
                #pragma unroll
                for (int p = 0; p < 4; p++) {
                    float lo, hi; unpack2(cb2[p], lo, hi);
                    cb_t[((2*p)*32 + chl0 + s)*40 + lane]   = cvt_tf32(lo);
                    cb_t[((2*p+1)*32 + chl0 + s)*40 + lane] = cvt_tf32(hi);
                }
            }
        }
        __syncthreads();

        // phase C: warp = head e; D += Wv_e^T @ cbar_e over this 32-ch chunk
        #pragma unroll
        for (int kt = 0; kt < 4; kt++) {
            uint32 bfr[4][2];
            #pragma unroll
            for (int n = 0; n < 4; n++) {
                bfr[n][0] = cb_t[(warp*32 + kt*8 + c4)*40 + n*8 + r4];
                bfr[n][1] = cb_t[(warp*32 + kt*8 + c4 + 4)*40 + n*8 + r4];
            }
            #pragma unroll
            for (int m = 0; m < 4; m++) {
                uint4 af = g_wvt[((warp*32 + cbk*4 + kt)*4 + m)*32 + lane];
                #pragma unroll
                for (int n = 0; n < 4; n++)
                    mma_tf32(D[m][n], (const uint32*)&af, bfr[n]);
            }
        }
        __syncthreads();
    }

    // ---- stage H as tf32 into hst[px][516 + d'] (stride 516: conflict-free) ----
    #pragma unroll
    for (int m = 0; m < 4; m++) {
        int d_lo = warp*HDIM + m*16 + r4;
        #pragma unroll
        for (int n = 0; n < 4; n++) {
            int pxa = n*8 + 2*c4;
            hst[pxa*516 + d_lo]           = cvt_tf32(D[m][n][0]);
            hst[(pxa+1)*516 + d_lo]       = cvt_tf32(D[m][n][1]);
            hst[pxa*516 + d_lo + 8]       = cvt_tf32(D[m][n][2]);
            hst[(pxa+1)*516 + d_lo + 8]   = cvt_tf32(D[m][n][3]);
        }
    }
    __syncthreads();

    // ---- out-GEMM via tf32 mma, af batched 4 kk deep ----
    float D2[2][4][4];
    #pragma unroll
    for (int m = 0; m < 2; m++)
        #pragma unroll
        for (int n = 0; n < 4; n++)
            #pragma unroll
            for (int t = 0; t < 4; t++) D2[m][n][t] = 0.f;

    #pragma unroll 1
    for (int g = 0; g < 16; g++) {
        uint4 af[8];
        #pragma unroll
        for (int j = 0; j < 4; j++) {
            int kk = g*4 + j;
            af[2*j]   = g_wot[(kk*16 + warp*2    )*32 + lane];
            af[2*j+1] = g_wot[(kk*16 + warp*2 + 1)*32 + lane];
        }
        #pragma unroll
        for (int j = 0; j < 4; j++) {
            int kk = g*4 + j;
            uint32 bfr[4][2];
            #pragma unroll
            for (int n = 0; n < 4; n++) {
                bfr[n][0] = hst[(n*8 + r4)*516 + kk*8 + c4];
                bfr[n][1] = hst[(n*8 + r4)*516 + kk*8 + c4 + 4];
            }
            #pragma unroll
            for (int n = 0; n < 4; n++) {
                mma_tf32(D2[0][n], (const uint32*)&af[2*j],   bfr[n]);
                mma_tf32(D2[1][n], (const uint32*)&af[2*j+1], bfr[n]);
            }
        }
    }

    // epilogue
    #pragma unroll
    for (int m = 0; m < 2; m++) {
        int co0 = warp*32 + m*16 + r4;
        float bl = b_out[co0], bh = b_out[co0 + 8];
        #pragma unroll
        for (int n = 0; n < 4; n++) {
            int px = n*8 + 2*c4;
            float* d0 = out + ((size_t)(b*HIDDEN + co0))*PIXB + h*WW + px;
            float* d1 = out + ((size_t)(b*HIDDEN + co0 + 8))*PIXB + h*WW + px;
            *(float2*)d0 = make_float2(D2[m][n][0] + bl, D2[m][n][1] + bl);
            *(float2*)d1 = make_float2(D2[m][n][2] + bh, D2[m][n][3] + bh);
        }
    }
}

// ---------------- launch ----------------
extern "C" void kernel_launch(void* const* d_in, const int* in_sizes, int n_in,
                              void* d_out, int out_size)
{
    const int*   q     = (const int*)  d_in[0];
    const float* c     = (const float*)d_in[1];
    const float* rms_w = (const float*)d_in[2];
    const float* emb   = (const float*)d_in[3];
    const float* w1    = (const float*)d_in[4];
    const float* b1    = (const float*)d_in[5];
    const float* w2    = (const float*)d_in[6];
    const float* b2    = (const float*)d_in[7];
    const float* w_kv  = (const float*)d_in[8];
    const float* w_out = (const float*)d_in[9];
    const float* b_out = (const float*)d_in[10];
    float* out = (float*)d_out;

    const int FRONT_SMEM = 16*264*4;        // 16896 B
    const int MID_SMEM   = 256*65*4;        // 66560 B
    const int ATTN_SMEM  = 33792 + 66560;   // 100352 B — 2 blocks/SM
    cudaFuncSetAttribute(k_front, cudaFuncAttributeMaxDynamicSharedMemorySize, FRONT_SMEM);
    cudaFuncSetAttribute(k_mid,   cudaFuncAttributeMaxDynamicSharedMemorySize, MID_SMEM);
    cudaFuncSetAttribute(k_attn3, cudaFuncAttributeMaxDynamicSharedMemorySize, ATTN_SMEM);

    k_front<<<64 + 64, 256, FRONT_SMEM>>>(w_kv, rms_w, q, emb, w1, b1, w_out);
    k_mid  <<<BATCH*NHEADS, 256, MID_SMEM>>>(w2, b2, w_kv, rms_w);
    k_attn3<<<BATCH*HH, 256, ATTN_SMEM>>>(c, b_out, out);
}